// round 17
// baseline (speedup 1.0000x reference)
#include <cuda_runtime.h>
#include <cstdint>
#include <cfloat>

// Exact FPS with warp-coherent geometric skipping.
// B=16, N=32768, M=2048. 8-CTA cluster/batch, NT=128. Each CTA Morton-sorts
// its 4096 pts (smem counting sort, one-time); 512 buckets of 8 consecutive
// pts; thread slot q holds bucket q*128+tid (warp-slot lanes own CONSECUTIVE
// buckets -> coherent skips). Per slot: conservative skip test vs cached
// (centroid, radius, maxd); fired buckets re-run the EXACT rn update and
// refresh a cached u64 key (val | ~gidx) preserving first-index ties.
// Exchange identical to R14 (proven): flat st.async b64 key + v2.b64 {xy,z}
// w/ complete_tx into 32B sector-exclusive slots, 1 txn barrier per buffer,
// emission in flight shadow. Winner slot found by full-key ballot.

constexpr int NPTS = 32768, MOUT = 2048, CS = 8;
constexpr int PCTA = NPTS / CS;       // 4096
constexpr int NT = 128, NW = 4, NSLOT = CS * NW;   // 32
constexpr int NQ = 4;                 // bucket slots / thread
constexpr unsigned TXB = (unsigned)NSLOT * 24u;

struct __align__(32) KSlot {
    unsigned long long key, pad, xy, z;
};
struct __align__(16) ClusterShm {
    unsigned long long mbar[2];
    KSlot skv[2][NSLOT];
    float4 cxyz[PCTA];                // NEGATED coords
    uint32_t counts[4096];
    uint32_t sorted[PCTA];
    uint32_t scanaux[NT];
};

__device__ __forceinline__ uint32_t smem_u32(const void* p) {
    return (uint32_t)__cvta_generic_to_shared(p);
}
__device__ __forceinline__ uint32_t mapa_u32(uint32_t a, uint32_t r) {
    uint32_t o; asm("mapa.shared::cluster.u32 %0, %1, %2;" : "=r"(o) : "r"(a), "r"(r)); return o;
}
__device__ __forceinline__ void mbar_wait_sleep(uint32_t a, uint32_t par) {
    asm volatile("{.reg .pred P; W%=: mbarrier.try_wait.parity.acquire.cta.shared::cta.b64 P,[%0],%1,0x989680; @!P bra W%=;}"
                 :: "r"(a), "r"(par) : "memory");
}
__device__ __forceinline__ unsigned long long pack2(float lo, float hi) {
    unsigned long long r; asm("mov.b64 %0, {%1, %2};" : "=l"(r) : "f"(lo), "f"(hi)); return r;
}
__device__ __forceinline__ void unpack2(unsigned long long v, float& lo, float& hi) {
    asm("mov.b64 {%0, %1}, %2;" : "=f"(lo), "=f"(hi) : "l"(v));
}
__device__ __forceinline__ unsigned long long addx2(unsigned long long a, unsigned long long b) {
    unsigned long long r; asm("add.rn.f32x2 %0, %1, %2;" : "=l"(r) : "l"(a), "l"(b)); return r;
}
__device__ __forceinline__ unsigned long long mulx2(unsigned long long a, unsigned long long b) {
    unsigned long long r; asm("mul.rn.f32x2 %0, %1, %2;" : "=l"(r) : "l"(a), "l"(b)); return r;
}
__device__ __forceinline__ float negf(float v) {
    return __uint_as_float(__float_as_uint(v) ^ 0x80000000u);
}
__device__ __forceinline__ uint32_t exp4(uint32_t v) {   // bits -> 0,3,6,9
    return (v & 1u) | ((v & 2u) << 2) | ((v & 4u) << 4) | ((v & 8u) << 6);
}
__device__ __forceinline__ uint32_t mcode(float4 nc) {   // from negated coords
    int cx = (int)fminf(15.f, fmaxf(0.f, (nc.x + 4.f) * 2.f));
    int cy = (int)fminf(15.f, fmaxf(0.f, (nc.y + 4.f) * 2.f));
    int cz = (int)fminf(15.f, fmaxf(0.f, (nc.z + 4.f) * 2.f));
    return exp4(cx) | (exp4(cy) << 1) | (exp4(cz) << 2);
}

__global__ void __launch_bounds__(NT, 1) __cluster_dims__(CS, 1, 1)
fps_kernel(const float* __restrict__ pts, float* __restrict__ out)
{
    extern __shared__ __align__(16) char shm_raw[];
    ClusterShm* s = reinterpret_cast<ClusterShm*>(shm_raw);
    const int tid = threadIdx.x;
    uint32_t rank; asm("mov.u32 %0, %%cluster_ctarank;" : "=r"(rank));
    const int batch = blockIdx.x / CS;
    const float* px = pts + (size_t)batch * 3u * NPTS;
    const float* py = px + NPTS;
    const float* pz = px + 2 * NPTS;
    float* ob = out + (size_t)batch * 3u * MOUT;

    const uint32_t mb0 = smem_u32(&s->mbar[0]);
    const uint32_t mb1 = smem_u32(&s->mbar[1]);
    if (tid == 0) {
        asm volatile("mbarrier.init.shared.b64 [%0], 1;" :: "r"(mb0) : "memory");
        asm volatile("mbarrier.init.shared.b64 [%0], 1;" :: "r"(mb1) : "memory");
        asm volatile("mbarrier.arrive.expect_tx.shared.b64 _, [%0], %1;" :: "r"(mb0), "r"(TXB) : "memory");
        asm volatile("mbarrier.arrive.expect_tx.shared.b64 _, [%0], %1;" :: "r"(mb1), "r"(TXB) : "memory");
    }

    // ---- setup: coords to smem (negated), Morton counting sort ----
    const int rankbase = (int)rank * PCTA;
#pragma unroll
    for (int k = 0; k < 32; ++k) {
        const int l = tid + k * NT, n = rankbase + l;
        s->cxyz[l] = make_float4(negf(px[n]), negf(py[n]), negf(pz[n]), 0.f);
        s->counts[tid * 32 + k] = 0;
    }
    __syncthreads();
    for (int k = 0; k < 32; ++k)
        atomicAdd(&s->counts[mcode(s->cxyz[tid + k * NT])], 1u);
    __syncthreads();
    {   // exclusive scan of counts[4096]
        uint32_t run = 0;
        for (int c = tid * 32; c < tid * 32 + 32; ++c) run += s->counts[c];
        s->scanaux[tid] = run;
        __syncthreads();
        if (tid == 0) {
            uint32_t r2 = 0;
            for (int t = 0; t < NT; ++t) { uint32_t v = s->scanaux[t]; s->scanaux[t] = r2; r2 += v; }
        }
        __syncthreads();
        run = s->scanaux[tid];
        for (int c = tid * 32; c < tid * 32 + 32; ++c) { uint32_t v = s->counts[c]; s->counts[c] = run; run += v; }
        __syncthreads();
    }
    for (int k = 0; k < 32; ++k) {
        const int l = tid + k * NT;
        const uint32_t pos = atomicAdd(&s->counts[mcode(s->cxyz[l])], 1u);
        s->sorted[pos] = (uint32_t)l;
    }
    __syncthreads();

    // ---- bucket state: slot q holds bucket q*128+tid (8 pts) ----
    unsigned long long X2[16], Y2[16], Z2[16];   // [4q+pair]
    float d[32];                                  // [8q+i]
    uint32_t gp[16];                              // packed lidx 2x16b [4q+i/2]
    unsigned long long bkey[NQ];
    float ncx[NQ], ncy[NQ], ncz[NQ], rad[NQ], rhs2[NQ];
#pragma unroll
    for (int q = 0; q < NQ; ++q) {
        const int beta = q * NT + tid;
        float xs[8], ys[8], zs[8];
        float ax = 0, ay = 0, az = 0;
#pragma unroll
        for (int i = 0; i < 8; ++i) {
            const uint32_t li = s->sorted[8 * beta + i];
            float4 c = s->cxyz[li];
            xs[i] = negf(c.x); ys[i] = negf(c.y); zs[i] = negf(c.z);
            ax += c.x; ay += c.y; az += c.z;     // negated centroid accum
            if (i & 1) gp[4 * q + i / 2] = (gp[4 * q + i / 2] & 0xFFFFu) | (li << 16);
            else       gp[4 * q + i / 2] = li;
            d[8 * q + i] = 1e10f;
        }
        ncx[q] = ax * 0.125f; ncy[q] = ay * 0.125f; ncz[q] = az * 0.125f;
        float rr = 0;
#pragma unroll
        for (int i = 0; i < 8; ++i) {
            float dx = negf(xs[i]) - ncx[q], dy = negf(ys[i]) - ncy[q], dz = negf(zs[i]) - ncz[q];
            rr = fmaxf(rr, dx * dx + dy * dy + dz * dz);
        }
        rad[q] = sqrtf(rr) * 1.002f;
        rhs2[q] = FLT_MAX;
        bkey[q] = 0;
#pragma unroll
        for (int i = 0; i < 4; ++i) {
            X2[4 * q + i] = pack2(xs[2 * i], xs[2 * i + 1]);
            Y2[4 * q + i] = pack2(ys[2 * i], ys[2 * i + 1]);
            Z2[4 * q + i] = pack2(zs[2 * i], zs[2 * i + 1]);
        }
    }
    float nlx = negf(px[0]), nly = negf(py[0]), nlz = negf(pz[0]);

    __syncthreads();
    asm volatile("barrier.cluster.arrive.aligned;" ::: "memory");
    asm volatile("barrier.cluster.wait.aligned;"   ::: "memory");

    const bool writer = (rank == 0u) && (tid == 0);
    const int lane = tid & 31;
    const int wid = tid >> 5;
    const uint32_t tr = (uint32_t)(lane & 7);
    const int myslot = (int)rank * NW + wid;
    uint32_t a_k[2], a_xz[2], a_mb[2];
#pragma unroll
    for (int b = 0; b < 2; ++b) {
        a_k[b]  = mapa_u32(smem_u32(&s->skv[b][myslot].key), tr);
        a_xz[b] = mapa_u32(smem_u32(&s->skv[b][myslot].xy),  tr);
        a_mb[b] = mapa_u32(b == 0 ? mb0 : mb1, tr);
    }

    for (int j = 0; j < MOUT - 1; ++j) {
        // ---- per-slot conservative skip tests ----
        bool fire[NQ];
#pragma unroll
        for (int q = 0; q < NQ; ++q) {
            const float a = ncx[q] - nlx, b2 = ncy[q] - nly, c2 = ncz[q] - nlz;
            fire[q] = (a * a + b2 * b2 + c2 * c2) < rhs2[q];
        }
        const unsigned long long nlx2 = pack2(nlx, nlx);
        const unsigned long long nly2 = pack2(nly, nly);
        const unsigned long long nlz2 = pack2(nlz, nlz);
#pragma unroll
        for (int q = 0; q < NQ; ++q) {
            if (__any_sync(0xFFFFFFFFu, fire[q])) {
                // exact rn update of this bucket's 8 points
#pragma unroll
                for (int i = 0; i < 4; ++i) {
                    unsigned long long dx = addx2(X2[4 * q + i], nlx2);
                    unsigned long long dy = addx2(Y2[4 * q + i], nly2);
                    unsigned long long dz = addx2(Z2[4 * q + i], nlz2);
                    unsigned long long dd = addx2(addx2(mulx2(dx, dx), mulx2(dy, dy)), mulx2(dz, dz));
                    float f0, f1; unpack2(dd, f0, f1);
                    d[8 * q + 2 * i]     = fminf(d[8 * q + 2 * i],     f0);
                    d[8 * q + 2 * i + 1] = fminf(d[8 * q + 2 * i + 1], f1);
                }
                float p0 = fmaxf(d[8 * q], d[8 * q + 1]), p1 = fmaxf(d[8 * q + 2], d[8 * q + 3]);
                float p2 = fmaxf(d[8 * q + 4], d[8 * q + 5]), p3 = fmaxf(d[8 * q + 6], d[8 * q + 7]);
                const float b8 = fmaxf(fmaxf(p0, p1), fmaxf(p2, p3));
                uint32_t bg = 0xFFFFFFFFu;
#pragma unroll
                for (int i = 0; i < 8; ++i) {
                    const uint32_t li = (gp[4 * q + i / 2] >> ((i & 1) * 16)) & 0xFFFFu;
                    if (d[8 * q + i] == b8) bg = min(bg, li);
                }
                bkey[q] = ((unsigned long long)__float_as_uint(b8) << 32) |
                          (unsigned long long)(0xFFFFFFFFu - (uint32_t)(rankbase + (int)bg));
                const float rh = sqrtf(b8) * 1.0001f + rad[q];
                rhs2[q] = rh * rh;
            }
        }
        // ---- thread key = max of 4 bucket keys; warp redux ----
        unsigned long long tk = bkey[0];
#pragma unroll
        for (int q = 1; q < NQ; ++q) if (bkey[q] > tk) tk = bkey[q];
        const uint32_t tval = (uint32_t)(tk >> 32), tinv = (uint32_t)tk;
        const uint32_t wval = __reduce_max_sync(0xFFFFFFFFu, tval);
        const uint32_t winv = __reduce_max_sync(0xFFFFFFFFu, (tval == wval) ? tinv : 0u);
        const uint32_t widx = 0xFFFFFFFFu - winv;

        // ---- winner coords (negated) via broadcast LDS.128; send ----
        const float4 wc = s->cxyz[(int)widx - rankbase];
        const unsigned long long ck = ((unsigned long long)wval << 32) | winv;
        const unsigned long long cxy = pack2(wc.x, wc.y);
        const unsigned long long cz = pack2(wc.z, 0.0f);
        const int buf = j & 1;
        const uint32_t parity = (uint32_t)(j >> 1) & 1u;
        asm volatile(
            "{.reg .pred p; setp.lt.u32 p, %0, 8;"
            "@p st.async.shared::cluster.mbarrier::complete_tx::bytes.b64 [%1], %3, [%2];"
            "@p st.async.shared::cluster.mbarrier::complete_tx::bytes.v2.b64 [%4], {%5, %6}, [%2];}"
            :: "r"((uint32_t)lane), "r"(a_k[buf]), "r"(a_mb[buf]),
               "l"(ck), "r"(a_xz[buf]), "l"(cxy), "l"(cz) : "memory");

        if (writer) {   // emit selection j inside the flight shadow
            ob[j] = negf(nlx); ob[MOUT + j] = negf(nly); ob[2 * MOUT + j] = negf(nlz);
        }
        mbar_wait_sleep(buf ? mb1 : mb0, parity);
        if (tid == 0) {
            asm volatile("mbarrier.arrive.expect_tx.shared.b64 _, [%0], %1;"
                         :: "r"(buf ? mb1 : mb0), "r"(TXB) : "memory");
        }
        // ---- 32-candidate reduce + winner slot by full-key ballot ----
        const unsigned long long m = s->skv[buf][lane].key;
        const uint32_t mv = (uint32_t)(m >> 32);
        const uint32_t gv = __reduce_max_sync(0xFFFFFFFFu, mv);
        const uint32_t ginv = __reduce_max_sync(0xFFFFFFFFu, (mv == gv) ? (uint32_t)m : 0u);
        const uint32_t bal = __ballot_sync(0xFFFFFFFFu, (mv == gv) && ((uint32_t)m == ginv));
        const int wslot = __ffs(bal) - 1;
        unsigned long long wxy, wz;
        asm volatile("ld.shared.v2.u64 {%0, %1}, [%2];"
                     : "=l"(wxy), "=l"(wz) : "r"(smem_u32(&s->skv[buf][wslot].xy)));
        float zlo, zhi;
        unpack2(wxy, nlx, nly);
        unpack2(wz, zlo, zhi);
        nlz = zlo;
    }
    if (writer) {
        ob[MOUT - 1] = negf(nlx); ob[2 * MOUT - 1] = negf(nly); ob[3 * MOUT - 1] = negf(nlz);
    }
    asm volatile("barrier.cluster.arrive.aligned;" ::: "memory");
    asm volatile("barrier.cluster.wait.aligned;"   ::: "memory");
}

extern "C" void kernel_launch(void* const* d_in, const int* in_sizes, int n_in,
                              void* d_out, int out_size)
{
    (void)n_in; (void)out_size;
    const float* pts = (const float*)d_in[0];
    float* out = (float*)d_out;
    const int B = in_sizes[0] / (3 * NPTS);
    const size_t shm = sizeof(ClusterShm);   // ~100 KB
    cudaFuncSetAttribute(fps_kernel, cudaFuncAttributeMaxDynamicSharedMemorySize, (int)shm);
    fps_kernel<<<B * CS, NT, shm>>>(pts, out);
}